// round 4
// baseline (speedup 1.0000x reference)
#include <cuda_runtime.h>
#include <math.h>

#define N_NODES 50000
#define N_EDGES 800000
#define M_Y 256

// ---------------- scratch (device globals; no allocation) ----------------
__device__ float g_bufA[N_NODES * 128];
__device__ float g_bufB[N_NODES * 128];
__device__ float g_di[N_NODES];
__device__ int   g_cnt[N_NODES];
__device__ int   g_cur[N_NODES];
__device__ int   g_row[N_NODES + 1];
__device__ int2  g_epack[N_EDGES];   // .x = src, .y = __float_as_int(norm)
__device__ float g_t[M_Y * 128];
__device__ int   g_is64;

// ---------------- packed fp32x2 FMA (2x FFMA throughput on sm_103a) ----
__device__ __forceinline__ unsigned long long ffma2(unsigned long long a,
                                                    unsigned long long b,
                                                    unsigned long long c) {
    unsigned long long d;
    asm("fma.rn.f32x2 %0, %1, %2, %3;" : "=l"(d) : "l"(a), "l"(b), "l"(c));
    return d;
}
__device__ __forceinline__ unsigned long long pack2(float a) {
    unsigned long long r;
    asm("mov.b64 %0, {%1, %1};" : "=l"(r) : "f"(a));
    return r;
}

// ---------------- init: zero counters + edge dtype detection ----------
__global__ void k_init(const unsigned int* __restrict__ w) {
    int i = blockIdx.x * blockDim.x + threadIdx.x;
    if (i < N_NODES) { g_cnt[i] = 0; g_cur[i] = 0; }
    if (blockIdx.x == 0) {
        __shared__ unsigned int acc;
        if (threadIdx.x == 0) acc = 0u;
        __syncthreads();
        unsigned int v = 0u;
        for (int j = threadIdx.x; j < 1024; j += blockDim.x) v |= w[2 * j + 1];
        atomicOr(&acc, v);
        __syncthreads();
        if (threadIdx.x == 0) g_is64 = (acc == 0u) ? 1 : 0;
    }
}

__device__ __forceinline__ int load_edge(const void* ei, long long idx) {
    if (g_is64) return (int)((const long long*)ei)[idx];
    return ((const int*)ei)[idx];
}

__global__ void k_count(const void* __restrict__ ei, int E) {
    int e = blockIdx.x * blockDim.x + threadIdx.x;
    if (e >= E) return;
    int d = load_edge(ei, (long long)E + e);
    if ((unsigned)d < (unsigned)N_NODES) atomicAdd(&g_cnt[d], 1);
}

// single-block fused scan: 1024 threads x 49 elements each
#define SCAN_CHUNK 49
__global__ void k_scan() {
    __shared__ int sm[2][1024];
    int t = threadIdx.x;
    int beg = t * SCAN_CHUNK;
    int end = beg + SCAN_CHUNK; if (end > N_NODES) end = N_NODES;
    int sum = 0;
    for (int i = beg; i < end; i++) sum += g_cnt[i];
    int buf = 0;
    sm[0][t] = sum;
    __syncthreads();
    for (int off = 1; off < 1024; off <<= 1) {
        int nv = sm[buf][t];
        if (t >= off) nv += sm[buf][t - off];
        sm[buf ^ 1][t] = nv;
        buf ^= 1;
        __syncthreads();
    }
    int run = sm[buf][t] - sum;  // exclusive prefix for this chunk
    for (int i = beg; i < end; i++) {
        int c = g_cnt[i];
        run += c;
        g_row[i + 1] = run;
        g_di[i] = rsqrtf((float)(c + 1));  // +1 self loop
    }
    if (t == 0) g_row[0] = 0;
}

__global__ void k_scatter(const void* __restrict__ ei, int E) {
    int e = blockIdx.x * blockDim.x + threadIdx.x;
    if (e >= E) return;
    int s = load_edge(ei, e);
    int d = load_edge(ei, (long long)E + e);
    if ((unsigned)s >= (unsigned)N_NODES || (unsigned)d >= (unsigned)N_NODES) return;
    int pos = g_row[d] + atomicAdd(&g_cur[d], 1);
    g_epack[pos] = make_int2(s, __float_as_int(g_di[s] * g_di[d]));
}

// ---------------- GEMM: C[n,FO] = A[n,128] @ W[128,FO] ----------------
template <int FO>
__global__ void k_gemm(const float* __restrict__ A, const float* __restrict__ W,
                       float* __restrict__ C, int n) {
    extern __shared__ float smf[];
    float* Ws = smf;               // 128*FO
    float* As = smf + 128 * FO;    // 32*132
    int row0 = blockIdx.x * 32;
    for (int i = threadIdx.x; i < 128 * FO / 4; i += 256)
        ((float4*)Ws)[i] = ((const float4*)W)[i];
    for (int i = threadIdx.x; i < 32 * 32; i += 256) {
        int r = i >> 5, c = i & 31;
        int gr = row0 + r;
        float4 v = (gr < n) ? ((const float4*)A)[(size_t)gr * 32 + c]
                            : make_float4(0.f, 0.f, 0.f, 0.f);
        *(float4*)(As + r * 132 + c * 4) = v;
    }
    __syncthreads();

    const int row = threadIdx.x & 31;
    const int c0 = (threadIdx.x >> 5) * (FO / 8);
    constexpr int NP = FO / 16;  // packed f32x2 accumulators per thread
    unsigned long long acc[NP];
#pragma unroll
    for (int q = 0; q < NP; q++) acc[q] = 0ull;

    const float* arow = As + row * 132;
#pragma unroll 2
    for (int k4 = 0; k4 < 128; k4 += 4) {
        float4 av = *(const float4*)(arow + k4);
        float as[4] = {av.x, av.y, av.z, av.w};
#pragma unroll
        for (int j = 0; j < 4; j++) {
            unsigned long long a2 = pack2(as[j]);
            const ulonglong2* wv = (const ulonglong2*)(Ws + (k4 + j) * FO + c0);
#pragma unroll
            for (int q = 0; q < NP / 2; q++) {
                ulonglong2 w = wv[q];
                acc[2 * q]     = ffma2(a2, w.x, acc[2 * q]);
                acc[2 * q + 1] = ffma2(a2, w.y, acc[2 * q + 1]);
            }
        }
    }
    int gr = row0 + row;
    if (gr < n) {
        float4* cv = (float4*)(C + (size_t)gr * FO + c0);
#pragma unroll
        for (int q = 0; q < NP / 2; q++) {
            union { unsigned long long u; float2 f; } u0, u1;
            u0.u = acc[2 * q]; u1.u = acc[2 * q + 1];
            cv[q] = make_float4(u0.f.x, u0.f.y, u1.f.x, u1.f.y);
        }
    }
}

// ---------------- aggregation (one warp per node, 4-way unroll) --------
__global__ void k_agg128(const float* __restrict__ h, const float* __restrict__ bias,
                         float* __restrict__ out, int n) {
    int node = (blockIdx.x * blockDim.x + threadIdx.x) >> 5;
    int lane = threadIdx.x & 31;
    if (node >= n) return;
    const float4* hp = (const float4*)h;
    float di = g_di[node];
    float sn = di * di;
    float4 acc = hp[(size_t)node * 32 + lane];
    acc.x *= sn; acc.y *= sn; acc.z *= sn; acc.w *= sn;
    int e = g_row[node], end = g_row[node + 1];
    for (; e + 3 < end; e += 4) {
        int2 p0 = g_epack[e];
        int2 p1 = g_epack[e + 1];
        int2 p2 = g_epack[e + 2];
        int2 p3 = g_epack[e + 3];
        float4 v0 = hp[(size_t)p0.x * 32 + lane];
        float4 v1 = hp[(size_t)p1.x * 32 + lane];
        float4 v2 = hp[(size_t)p2.x * 32 + lane];
        float4 v3 = hp[(size_t)p3.x * 32 + lane];
        float w0 = __int_as_float(p0.y), w1 = __int_as_float(p1.y);
        float w2 = __int_as_float(p2.y), w3 = __int_as_float(p3.y);
        acc.x = fmaf(v0.x, w0, acc.x); acc.y = fmaf(v0.y, w0, acc.y);
        acc.z = fmaf(v0.z, w0, acc.z); acc.w = fmaf(v0.w, w0, acc.w);
        acc.x = fmaf(v1.x, w1, acc.x); acc.y = fmaf(v1.y, w1, acc.y);
        acc.z = fmaf(v1.z, w1, acc.z); acc.w = fmaf(v1.w, w1, acc.w);
        acc.x = fmaf(v2.x, w2, acc.x); acc.y = fmaf(v2.y, w2, acc.y);
        acc.z = fmaf(v2.z, w2, acc.z); acc.w = fmaf(v2.w, w2, acc.w);
        acc.x = fmaf(v3.x, w3, acc.x); acc.y = fmaf(v3.y, w3, acc.y);
        acc.z = fmaf(v3.z, w3, acc.z); acc.w = fmaf(v3.w, w3, acc.w);
    }
    for (; e < end; e++) {
        int2 p = g_epack[e];
        float4 v = hp[(size_t)p.x * 32 + lane];
        float wt = __int_as_float(p.y);
        acc.x = fmaf(v.x, wt, acc.x); acc.y = fmaf(v.y, wt, acc.y);
        acc.z = fmaf(v.z, wt, acc.z); acc.w = fmaf(v.w, wt, acc.w);
    }
    float4 b = ((const float4*)bias)[lane];
    acc.x = fmaxf(acc.x + b.x, 0.f);
    acc.y = fmaxf(acc.y + b.y, 0.f);
    acc.z = fmaxf(acc.z + b.z, 0.f);
    acc.w = fmaxf(acc.w + b.w, 0.f);
    ((float4*)out)[(size_t)node * 32 + lane] = acc;
}

// layer 3: aggregate (F=64) + bias + row L2-normalize -> final x_emb.
__global__ void k_agg64n(const float* __restrict__ h, const float* __restrict__ bias,
                         float* __restrict__ out, int n) {
    int node = (blockIdx.x * blockDim.x + threadIdx.x) >> 5;
    int lane = threadIdx.x & 31;
    if (node >= n) return;
    const float2* hp = (const float2*)h;
    float di = g_di[node];
    float sn = di * di;
    float2 acc = hp[(size_t)node * 32 + lane];
    acc.x *= sn; acc.y *= sn;
    int e = g_row[node], end = g_row[node + 1];
    for (; e + 3 < end; e += 4) {
        int2 p0 = g_epack[e];
        int2 p1 = g_epack[e + 1];
        int2 p2 = g_epack[e + 2];
        int2 p3 = g_epack[e + 3];
        float2 v0 = hp[(size_t)p0.x * 32 + lane];
        float2 v1 = hp[(size_t)p1.x * 32 + lane];
        float2 v2 = hp[(size_t)p2.x * 32 + lane];
        float2 v3 = hp[(size_t)p3.x * 32 + lane];
        float w0 = __int_as_float(p0.y), w1 = __int_as_float(p1.y);
        float w2 = __int_as_float(p2.y), w3 = __int_as_float(p3.y);
        acc.x = fmaf(v0.x, w0, acc.x); acc.y = fmaf(v0.y, w0, acc.y);
        acc.x = fmaf(v1.x, w1, acc.x); acc.y = fmaf(v1.y, w1, acc.y);
        acc.x = fmaf(v2.x, w2, acc.x); acc.y = fmaf(v2.y, w2, acc.y);
        acc.x = fmaf(v3.x, w3, acc.x); acc.y = fmaf(v3.y, w3, acc.y);
    }
    for (; e < end; e++) {
        int2 p = g_epack[e];
        float2 v = hp[(size_t)p.x * 32 + lane];
        float wt = __int_as_float(p.y);
        acc.x = fmaf(v.x, wt, acc.x); acc.y = fmaf(v.y, wt, acc.y);
    }
    float2 b = ((const float2*)bias)[lane];
    acc.x += b.x;
    acc.y += b.y;
    float ss = acc.x * acc.x + acc.y * acc.y;
#pragma unroll
    for (int o = 16; o; o >>= 1) ss += __shfl_xor_sync(0xffffffffu, ss, o);
    float inv = 1.f / fmaxf(sqrtf(ss), 1e-12f);
    ((float2*)out)[(size_t)node * 32 + lane] = make_float2(acc.x * inv, acc.y * inv);
}

// ---------------- y branch ----------------
__global__ void k_y1(const float* __restrict__ y, const float* __restrict__ gamma,
                     const float* __restrict__ beta, const float* __restrict__ Wm1,
                     const float* __restrict__ bm1) {
    __shared__ float red[256];
    int t = threadIdx.x;
    float v = y[t];
    red[t] = v;
    __syncthreads();
    for (int s = 128; s; s >>= 1) { if (t < s) red[t] += red[t + s]; __syncthreads(); }
    float mu = red[0] * (1.f / 256.f);
    __syncthreads();
    red[t] = v * v;
    __syncthreads();
    for (int s = 128; s; s >>= 1) { if (t < s) red[t] += red[t + s]; __syncthreads(); }
    float var = red[0] * (1.f / 256.f) - mu * mu;
    float yb = (v - mu) * rsqrtf(var + 1e-5f) * gamma[0] + beta[0];
    for (int j = 0; j < 128; j++)
        g_t[t * 128 + j] = fmaxf(fmaf(yb, Wm1[j], bm1[j]), 0.f);
}

__global__ void k_y2(const float* __restrict__ Wm2, const float* __restrict__ bm2,
                     float* __restrict__ out) {
    __shared__ float ts[128];
    __shared__ float wsum[2];
    int i = blockIdx.x, c = threadIdx.x;
    ts[c] = g_t[i * 128 + c];
    ts[c + 64] = g_t[i * 128 + c + 64];
    __syncthreads();
    float a = bm2[c];
#pragma unroll 4
    for (int j = 0; j < 128; j++) a = fmaf(ts[j], Wm2[j * 64 + c], a);
    float ss = a * a;
#pragma unroll
    for (int o = 16; o; o >>= 1) ss += __shfl_xor_sync(0xffffffffu, ss, o);
    if ((c & 31) == 0) wsum[c >> 5] = ss;
    __syncthreads();
    float inv = 1.f / fmaxf(sqrtf(wsum[0] + wsum[1]), 1e-12f);
    out[i * 64 + c] = a * inv;
}

// ---------------- launch ----------------
extern "C" void kernel_launch(void* const* d_in, const int* in_sizes, int n_in,
                              void* d_out, int out_size) {
    const float* x  = (const float*)d_in[0];
    const float* y  = (const float*)d_in[1];
    const void*  ei = d_in[2];
    const float* W1 = (const float*)d_in[3];  const float* b1  = (const float*)d_in[4];
    const float* W2 = (const float*)d_in[5];  const float* b2  = (const float*)d_in[6];
    const float* W3 = (const float*)d_in[7];  const float* b3  = (const float*)d_in[8];
    const float* bg = (const float*)d_in[9];  const float* bb  = (const float*)d_in[10];
    const float* Wm1 = (const float*)d_in[11]; const float* bm1 = (const float*)d_in[12];
    const float* Wm2 = (const float*)d_in[13]; const float* bm2 = (const float*)d_in[14];
    float* out = (float*)d_out;

    const int n = N_NODES;
    const int E = in_sizes[2] / 2;

    const size_t sm128 = 128 * 128 * 4 + 32 * 132 * 4;
    const size_t sm64  = 128 * 64 * 4 + 32 * 132 * 4;
    cudaFuncSetAttribute(k_gemm<128>, cudaFuncAttributeMaxDynamicSharedMemorySize, (int)sm128);
    cudaFuncSetAttribute(k_gemm<64>,  cudaFuncAttributeMaxDynamicSharedMemorySize, (int)sm64);

    void *pA, *pB;
    cudaGetSymbolAddress(&pA, g_bufA);
    cudaGetSymbolAddress(&pB, g_bufB);
    float* bufA = (float*)pA;
    float* bufB = (float*)pB;

    const int gb = (n + 31) / 32;
    const int aggBlocks = (n * 32 + 255) / 256;

    // fork: side stream runs GEMM1 + y-branch concurrently with CSR build
    cudaStream_t s2;
    cudaEvent_t evFork, evJoin;
    cudaStreamCreateWithFlags(&s2, cudaStreamNonBlocking);
    cudaEventCreateWithFlags(&evFork, cudaEventDisableTiming);
    cudaEventCreateWithFlags(&evJoin, cudaEventDisableTiming);

    cudaEventRecord(evFork, 0);
    cudaStreamWaitEvent(s2, evFork, 0);

    // side stream: GEMM1 (x @ W1) and the whole y branch
    k_gemm<128><<<gb, 256, sm128, s2>>>(x, W1, bufA, n);
    k_y1<<<1, 256, 0, s2>>>(y, bg, bb, Wm1, bm1);
    k_y2<<<M_Y, 64, 0, s2>>>(Wm2, bm2, out + (size_t)N_NODES * 64);
    cudaEventRecord(evJoin, s2);

    // main stream: CSR build
    k_init<<<(n + 255) / 256, 256>>>((const unsigned int*)ei);
    k_count<<<(E + 255) / 256, 256>>>(ei, E);
    k_scan<<<1, 1024>>>();
    k_scatter<<<(E + 255) / 256, 256>>>(ei, E);

    // join
    cudaStreamWaitEvent(0, evJoin, 0);

    // layer 1 aggregation, then the rest of the chain
    k_agg128<<<aggBlocks, 256>>>(bufA, b1, bufB, n);
    k_gemm<128><<<gb, 256, sm128>>>(bufB, W2, bufA, n);
    k_agg128<<<aggBlocks, 256>>>(bufA, b2, bufB, n);
    k_gemm<64><<<gb, 256, sm64>>>(bufB, W3, bufA, n);
    k_agg64n<<<aggBlocks, 256>>>(bufA, b3, out, n);

    cudaEventDestroy(evFork);
    cudaEventDestroy(evJoin);
    cudaStreamDestroy(s2);
}

// round 5
// speedup vs baseline: 1.2976x; 1.2976x over previous
#include <cuda_runtime.h>
#include <cuda_fp16.h>
#include <math.h>

#define N_NODES 50000
#define N_EDGES 800000
#define M_Y 256

// ---------------- scratch (device globals; no allocation) ----------------
__device__ float  g_bufA[N_NODES * 128];   // agg outputs (fp32, GEMM inputs)
__device__ __half g_h16[N_NODES * 128];    // GEMM outputs (fp16, agg gather src)
__device__ float  g_di[N_NODES];
__device__ int    g_cnt[N_NODES];
__device__ int    g_cur[N_NODES];
__device__ int    g_row[N_NODES + 1];
__device__ int2   g_epack[N_EDGES];        // .x = src, .y = __float_as_int(norm)
__device__ int    g_bsums[64];
__device__ int    g_boffs[64];
__device__ float  g_t[M_Y * 128];
__device__ int    g_is64;

// ---------------- packed fp32x2 FMA (2x FFMA throughput on sm_103a) ----
__device__ __forceinline__ unsigned long long ffma2(unsigned long long a,
                                                    unsigned long long b,
                                                    unsigned long long c) {
    unsigned long long d;
    asm("fma.rn.f32x2 %0, %1, %2, %3;" : "=l"(d) : "l"(a), "l"(b), "l"(c));
    return d;
}
__device__ __forceinline__ unsigned long long pack2(float a) {
    unsigned long long r;
    asm("mov.b64 %0, {%1, %1};" : "=l"(r) : "f"(a));
    return r;
}

// ---------------- init: zero counters + edge dtype detection ----------
__global__ void k_init(const unsigned int* __restrict__ w) {
    int i = blockIdx.x * blockDim.x + threadIdx.x;
    if (i < N_NODES) { g_cnt[i] = 0; g_cur[i] = 0; }
    if (blockIdx.x == 0) {
        __shared__ unsigned int acc;
        if (threadIdx.x == 0) acc = 0u;
        __syncthreads();
        unsigned int v = 0u;
        for (int j = threadIdx.x; j < 1024; j += blockDim.x) v |= w[2 * j + 1];
        atomicOr(&acc, v);
        __syncthreads();
        if (threadIdx.x == 0) g_is64 = (acc == 0u) ? 1 : 0;
    }
}

__device__ __forceinline__ int load_edge(const void* ei, long long idx) {
    if (g_is64) return (int)((const long long*)ei)[idx];
    return ((const int*)ei)[idx];
}

__global__ void k_count(const void* __restrict__ ei, int E) {
    int e = blockIdx.x * blockDim.x + threadIdx.x;
    if (e >= E) return;
    int d = load_edge(ei, (long long)E + e);
    if ((unsigned)d < (unsigned)N_NODES) atomicAdd(&g_cnt[d], 1);
}

// coalesced 3-phase scan (proven 5us in R3)
__global__ void k_scan1() {
    __shared__ int sm[2][1024];
    int t = threadIdx.x;
    int gid = blockIdx.x * 1024 + t;
    int v = (gid < N_NODES) ? g_cnt[gid] : 0;
    int buf = 0;
    sm[0][t] = v;
    __syncthreads();
    for (int off = 1; off < 1024; off <<= 1) {
        int nv = sm[buf][t];
        if (t >= off) nv += sm[buf][t - off];
        sm[buf ^ 1][t] = nv;
        buf ^= 1;
        __syncthreads();
    }
    int inc = sm[buf][t];
    if (gid < N_NODES) g_row[gid + 1] = inc;
    if (t == 1023) g_bsums[blockIdx.x] = inc;
}

__global__ void k_scan2(int nb) {
    if (threadIdx.x == 0 && blockIdx.x == 0) {
        int acc = 0;
        for (int b = 0; b < nb; b++) { g_boffs[b] = acc; acc += g_bsums[b]; }
    }
}

__global__ void k_scan3() {
    int gid = blockIdx.x * 1024 + threadIdx.x;
    if (gid < N_NODES) {
        g_row[gid + 1] += g_boffs[blockIdx.x];
        g_di[gid] = rsqrtf((float)(g_cnt[gid] + 1));  // +1 self loop
    }
    if (gid == 0) g_row[0] = 0;
}

__global__ void k_scatter(const void* __restrict__ ei, int E) {
    int e = blockIdx.x * blockDim.x + threadIdx.x;
    if (e >= E) return;
    int s = load_edge(ei, e);
    int d = load_edge(ei, (long long)E + e);
    if ((unsigned)s >= (unsigned)N_NODES || (unsigned)d >= (unsigned)N_NODES) return;
    int pos = g_row[d] + atomicAdd(&g_cur[d], 1);
    g_epack[pos] = make_int2(s, __float_as_int(g_di[s] * g_di[d]));
}

// ---------------- GEMM: H16[n,FO] = A[n,128] @ W[128,FO] (fp16 out) ----
template <int FO>
__global__ void k_gemm(const float* __restrict__ A, const float* __restrict__ W,
                       __half* __restrict__ H, int n) {
    extern __shared__ float smf[];
    float* Ws = smf;               // 128*FO
    float* As = smf + 128 * FO;    // 32*132
    int row0 = blockIdx.x * 32;
    for (int i = threadIdx.x; i < 128 * FO / 4; i += 256)
        ((float4*)Ws)[i] = ((const float4*)W)[i];
    for (int i = threadIdx.x; i < 32 * 32; i += 256) {
        int r = i >> 5, c = i & 31;
        int gr = row0 + r;
        float4 v = (gr < n) ? ((const float4*)A)[(size_t)gr * 32 + c]
                            : make_float4(0.f, 0.f, 0.f, 0.f);
        *(float4*)(As + r * 132 + c * 4) = v;
    }
    __syncthreads();

    const int row = threadIdx.x & 31;
    const int c0 = (threadIdx.x >> 5) * (FO / 8);
    constexpr int NP = FO / 16;  // packed f32x2 accumulators per thread
    unsigned long long acc[NP];
#pragma unroll
    for (int q = 0; q < NP; q++) acc[q] = 0ull;

    const float* arow = As + row * 132;
#pragma unroll 2
    for (int k4 = 0; k4 < 128; k4 += 4) {
        float4 av = *(const float4*)(arow + k4);
        float as[4] = {av.x, av.y, av.z, av.w};
#pragma unroll
        for (int j = 0; j < 4; j++) {
            unsigned long long a2 = pack2(as[j]);
            const ulonglong2* wv = (const ulonglong2*)(Ws + (k4 + j) * FO + c0);
#pragma unroll
            for (int q = 0; q < NP / 2; q++) {
                ulonglong2 w = wv[q];
                acc[2 * q]     = ffma2(a2, w.x, acc[2 * q]);
                acc[2 * q + 1] = ffma2(a2, w.y, acc[2 * q + 1]);
            }
        }
    }
    int gr = row0 + row;
    if (gr < n) {
        // convert each f32x2 accumulator to one half2, store vectorized
        unsigned int hv[NP];
#pragma unroll
        for (int q = 0; q < NP; q++) {
            union { unsigned long long u; float2 f; } uu;
            uu.u = acc[q];
            __half2 h2 = __float22half2_rn(uu.f);
            hv[q] = *(unsigned int*)&h2;
        }
        unsigned int* hp = (unsigned int*)(H + (size_t)gr * FO + c0);
#pragma unroll
        for (int q = 0; q < NP / 4; q++)
            ((uint4*)hp)[q] = make_uint4(hv[4 * q], hv[4 * q + 1], hv[4 * q + 2], hv[4 * q + 3]);
    }
}

// ---------------- aggregation (one warp per node, fp16 gathers) --------
// lane handles features 4*lane..4*lane+3 : one uint2 (2x half2) per edge.
__global__ void k_agg128(const __half* __restrict__ h, const float* __restrict__ bias,
                         float* __restrict__ out, int n) {
    int node = (blockIdx.x * blockDim.x + threadIdx.x) >> 5;
    int lane = threadIdx.x & 31;
    if (node >= n) return;
    const uint2* hp = (const uint2*)h;
    float di = g_di[node];
    float sn = di * di;
    uint2 su = hp[(size_t)node * 32 + lane];
    float2 s0 = __half22float2(*(const __half2*)&su.x);
    float2 s1 = __half22float2(*(const __half2*)&su.y);
    float4 acc = make_float4(s0.x * sn, s0.y * sn, s1.x * sn, s1.y * sn);
    int e = g_row[node], end = g_row[node + 1];
    for (; e + 3 < end; e += 4) {
        int2 p0 = g_epack[e];
        int2 p1 = g_epack[e + 1];
        int2 p2 = g_epack[e + 2];
        int2 p3 = g_epack[e + 3];
        uint2 u0 = hp[(size_t)p0.x * 32 + lane];
        uint2 u1 = hp[(size_t)p1.x * 32 + lane];
        uint2 u2 = hp[(size_t)p2.x * 32 + lane];
        uint2 u3 = hp[(size_t)p3.x * 32 + lane];
        float w0 = __int_as_float(p0.y), w1 = __int_as_float(p1.y);
        float w2 = __int_as_float(p2.y), w3 = __int_as_float(p3.y);
        {
            float2 a = __half22float2(*(const __half2*)&u0.x);
            float2 b = __half22float2(*(const __half2*)&u0.y);
            acc.x = fmaf(a.x, w0, acc.x); acc.y = fmaf(a.y, w0, acc.y);
            acc.z = fmaf(b.x, w0, acc.z); acc.w = fmaf(b.y, w0, acc.w);
        }
        {
            float2 a = __half22float2(*(const __half2*)&u1.x);
            float2 b = __half22float2(*(const __half2*)&u1.y);
            acc.x = fmaf(a.x, w1, acc.x); acc.y = fmaf(a.y, w1, acc.y);
            acc.z = fmaf(b.x, w1, acc.z); acc.w = fmaf(b.y, w1, acc.w);
        }
        {
            float2 a = __half22float2(*(const __half2*)&u2.x);
            float2 b = __half22float2(*(const __half2*)&u2.y);
            acc.x = fmaf(a.x, w2, acc.x); acc.y = fmaf(a.y, w2, acc.y);
            acc.z = fmaf(b.x, w2, acc.z); acc.w = fmaf(b.y, w2, acc.w);
        }
        {
            float2 a = __half22float2(*(const __half2*)&u3.x);
            float2 b = __half22float2(*(const __half2*)&u3.y);
            acc.x = fmaf(a.x, w3, acc.x); acc.y = fmaf(a.y, w3, acc.y);
            acc.z = fmaf(b.x, w3, acc.z); acc.w = fmaf(b.y, w3, acc.w);
        }
    }
    for (; e < end; e++) {
        int2 p = g_epack[e];
        uint2 u = hp[(size_t)p.x * 32 + lane];
        float wt = __int_as_float(p.y);
        float2 a = __half22float2(*(const __half2*)&u.x);
        float2 b = __half22float2(*(const __half2*)&u.y);
        acc.x = fmaf(a.x, wt, acc.x); acc.y = fmaf(a.y, wt, acc.y);
        acc.z = fmaf(b.x, wt, acc.z); acc.w = fmaf(b.y, wt, acc.w);
    }
    float4 b = ((const float4*)bias)[lane];
    acc.x = fmaxf(acc.x + b.x, 0.f);
    acc.y = fmaxf(acc.y + b.y, 0.f);
    acc.z = fmaxf(acc.z + b.z, 0.f);
    acc.w = fmaxf(acc.w + b.w, 0.f);
    ((float4*)out)[(size_t)node * 32 + lane] = acc;
}

// layer 3: aggregate (F=64, fp16 gathers) + bias + L2-normalize -> x_emb.
// lane handles features 2*lane, 2*lane+1 : one half2 per edge.
__global__ void k_agg64n(const __half* __restrict__ h, const float* __restrict__ bias,
                         float* __restrict__ out, int n) {
    int node = (blockIdx.x * blockDim.x + threadIdx.x) >> 5;
    int lane = threadIdx.x & 31;
    if (node >= n) return;
    const unsigned int* hp = (const unsigned int*)h;
    float di = g_di[node];
    float sn = di * di;
    unsigned int su = hp[(size_t)node * 32 + lane];
    float2 sf = __half22float2(*(const __half2*)&su);
    float2 acc = make_float2(sf.x * sn, sf.y * sn);
    int e = g_row[node], end = g_row[node + 1];
    for (; e + 3 < end; e += 4) {
        int2 p0 = g_epack[e];
        int2 p1 = g_epack[e + 1];
        int2 p2 = g_epack[e + 2];
        int2 p3 = g_epack[e + 3];
        unsigned int u0 = hp[(size_t)p0.x * 32 + lane];
        unsigned int u1 = hp[(size_t)p1.x * 32 + lane];
        unsigned int u2 = hp[(size_t)p2.x * 32 + lane];
        unsigned int u3 = hp[(size_t)p3.x * 32 + lane];
        float w0 = __int_as_float(p0.y), w1 = __int_as_float(p1.y);
        float w2 = __int_as_float(p2.y), w3 = __int_as_float(p3.y);
        float2 v0 = __half22float2(*(const __half2*)&u0);
        float2 v1 = __half22float2(*(const __half2*)&u1);
        float2 v2 = __half22float2(*(const __half2*)&u2);
        float2 v3 = __half22float2(*(const __half2*)&u3);
        acc.x = fmaf(v0.x, w0, acc.x); acc.y = fmaf(v0.y, w0, acc.y);
        acc.x = fmaf(v1.x, w1, acc.x); acc.y = fmaf(v1.y, w1, acc.y);
        acc.x = fmaf(v2.x, w2, acc.x); acc.y = fmaf(v2.y, w2, acc.y);
        acc.x = fmaf(v3.x, w3, acc.x); acc.y = fmaf(v3.y, w3, acc.y);
    }
    for (; e < end; e++) {
        int2 p = g_epack[e];
        unsigned int u = hp[(size_t)p.x * 32 + lane];
        float wt = __int_as_float(p.y);
        float2 v = __half22float2(*(const __half2*)&u);
        acc.x = fmaf(v.x, wt, acc.x); acc.y = fmaf(v.y, wt, acc.y);
    }
    float2 b = ((const float2*)bias)[lane];
    acc.x += b.x;
    acc.y += b.y;
    float ss = acc.x * acc.x + acc.y * acc.y;
#pragma unroll
    for (int o = 16; o; o >>= 1) ss += __shfl_xor_sync(0xffffffffu, ss, o);
    float inv = 1.f / fmaxf(sqrtf(ss), 1e-12f);
    ((float2*)out)[(size_t)node * 32 + lane] = make_float2(acc.x * inv, acc.y * inv);
}

// ---------------- y branch ----------------
__global__ void k_y1(const float* __restrict__ y, const float* __restrict__ gamma,
                     const float* __restrict__ beta, const float* __restrict__ Wm1,
                     const float* __restrict__ bm1) {
    __shared__ float red[256];
    int t = threadIdx.x;
    float v = y[t];
    red[t] = v;
    __syncthreads();
    for (int s = 128; s; s >>= 1) { if (t < s) red[t] += red[t + s]; __syncthreads(); }
    float mu = red[0] * (1.f / 256.f);
    __syncthreads();
    red[t] = v * v;
    __syncthreads();
    for (int s = 128; s; s >>= 1) { if (t < s) red[t] += red[t + s]; __syncthreads(); }
    float var = red[0] * (1.f / 256.f) - mu * mu;
    float yb = (v - mu) * rsqrtf(var + 1e-5f) * gamma[0] + beta[0];
    for (int j = 0; j < 128; j++)
        g_t[t * 128 + j] = fmaxf(fmaf(yb, Wm1[j], bm1[j]), 0.f);
}

__global__ void k_y2(const float* __restrict__ Wm2, const float* __restrict__ bm2,
                     float* __restrict__ out) {
    __shared__ float ts[128];
    __shared__ float wsum[2];
    int i = blockIdx.x, c = threadIdx.x;
    ts[c] = g_t[i * 128 + c];
    ts[c + 64] = g_t[i * 128 + c + 64];
    __syncthreads();
    float a = bm2[c];
#pragma unroll 4
    for (int j = 0; j < 128; j++) a = fmaf(ts[j], Wm2[j * 64 + c], a);
    float ss = a * a;
#pragma unroll
    for (int o = 16; o; o >>= 1) ss += __shfl_xor_sync(0xffffffffu, ss, o);
    if ((c & 31) == 0) wsum[c >> 5] = ss;
    __syncthreads();
    float inv = 1.f / fmaxf(sqrtf(wsum[0] + wsum[1]), 1e-12f);
    out[i * 64 + c] = a * inv;
}

// ---------------- launch ----------------
extern "C" void kernel_launch(void* const* d_in, const int* in_sizes, int n_in,
                              void* d_out, int out_size) {
    const float* x  = (const float*)d_in[0];
    const float* y  = (const float*)d_in[1];
    const void*  ei = d_in[2];
    const float* W1 = (const float*)d_in[3];  const float* b1  = (const float*)d_in[4];
    const float* W2 = (const float*)d_in[5];  const float* b2  = (const float*)d_in[6];
    const float* W3 = (const float*)d_in[7];  const float* b3  = (const float*)d_in[8];
    const float* bg = (const float*)d_in[9];  const float* bb  = (const float*)d_in[10];
    const float* Wm1 = (const float*)d_in[11]; const float* bm1 = (const float*)d_in[12];
    const float* Wm2 = (const float*)d_in[13]; const float* bm2 = (const float*)d_in[14];
    float* out = (float*)d_out;

    const int n = N_NODES;
    const int E = in_sizes[2] / 2;

    const size_t sm128 = 128 * 128 * 4 + 32 * 132 * 4;
    const size_t sm64  = 128 * 64 * 4 + 32 * 132 * 4;
    cudaFuncSetAttribute(k_gemm<128>, cudaFuncAttributeMaxDynamicSharedMemorySize, (int)sm128);
    cudaFuncSetAttribute(k_gemm<64>,  cudaFuncAttributeMaxDynamicSharedMemorySize, (int)sm64);

    void *pA, *pH;
    cudaGetSymbolAddress(&pA, g_bufA);
    cudaGetSymbolAddress(&pH, g_h16);
    float*  bufA = (float*)pA;
    __half* h16  = (__half*)pH;

    const int gb = (n + 31) / 32;
    const int aggBlocks = (n * 32 + 255) / 256;
    const int NB = (n + 1023) / 1024;  // 49

    // fork: side stream runs GEMM1 + y-branch concurrently with CSR build
    cudaStream_t s2;
    cudaEvent_t evFork, evJoin;
    cudaStreamCreateWithFlags(&s2, cudaStreamNonBlocking);
    cudaEventCreateWithFlags(&evFork, cudaEventDisableTiming);
    cudaEventCreateWithFlags(&evJoin, cudaEventDisableTiming);

    cudaEventRecord(evFork, 0);
    cudaStreamWaitEvent(s2, evFork, 0);

    k_gemm<128><<<gb, 256, sm128, s2>>>(x, W1, h16, n);
    k_y1<<<1, 256, 0, s2>>>(y, bg, bb, Wm1, bm1);
    k_y2<<<M_Y, 64, 0, s2>>>(Wm2, bm2, out + (size_t)N_NODES * 64);
    cudaEventRecord(evJoin, s2);

    // main stream: CSR build
    k_init<<<(n + 255) / 256, 256>>>((const unsigned int*)ei);
    k_count<<<(E + 255) / 256, 256>>>(ei, E);
    k_scan1<<<NB, 1024>>>();
    k_scan2<<<1, 32>>>(NB);
    k_scan3<<<NB, 1024>>>();
    k_scatter<<<(E + 255) / 256, 256>>>(ei, E);

    cudaStreamWaitEvent(0, evJoin, 0);

    // layer 1 aggregation, then the rest of the chain
    k_agg128<<<aggBlocks, 256>>>(h16, b1, bufA, n);
    k_gemm<128><<<gb, 256, sm128>>>(bufA, W2, h16, n);
    k_agg128<<<aggBlocks, 256>>>(h16, b2, bufA, n);
    k_gemm<64><<<gb, 256, sm64>>>(bufA, W3, h16, n);
    k_agg64n<<<aggBlocks, 256>>>(h16, b3, out, n);

    cudaEventDestroy(evFork);
    cudaEventDestroy(evJoin);
    cudaStreamDestroy(s2);
}

// round 6
// speedup vs baseline: 1.3015x; 1.0030x over previous
#include <cuda_runtime.h>
#include <cuda_fp16.h>
#include <math.h>

#define N_NODES 50000
#define N_EDGES 800000
#define M_Y 256

// ---------------- scratch (device globals; no allocation) ----------------
__device__ __half g_h16a[N_NODES * 128];
__device__ __half g_h16b[N_NODES * 128];
__device__ float  g_di[N_NODES];
__device__ int    g_cnt[N_NODES];
__device__ int    g_cur[N_NODES];
__device__ int    g_row[N_NODES + 1];
__device__ int2   g_epack[N_EDGES];   // .x = src, .y = __float_as_int(norm)
__device__ int    g_bsums[64];
__device__ int    g_boffs[64];
__device__ float  g_t[M_Y * 128];
__device__ int    g_is64;

// ---------------- packed fp32x2 FMA (2x FFMA throughput on sm_103a) ----
__device__ __forceinline__ unsigned long long ffma2(unsigned long long a,
                                                    unsigned long long b,
                                                    unsigned long long c) {
    unsigned long long d;
    asm("fma.rn.f32x2 %0, %1, %2, %3;" : "=l"(d) : "l"(a), "l"(b), "l"(c));
    return d;
}
__device__ __forceinline__ unsigned long long pack2(float a) {
    unsigned long long r;
    asm("mov.b64 %0, {%1, %1};" : "=l"(r) : "f"(a));
    return r;
}

// ---------------- init: zero counters + edge dtype detection ----------
__global__ void k_init(const unsigned int* __restrict__ w) {
    int i = blockIdx.x * blockDim.x + threadIdx.x;
    if (i < N_NODES) { g_cnt[i] = 0; g_cur[i] = 0; }
    if (blockIdx.x == 0) {
        __shared__ unsigned int acc;
        if (threadIdx.x == 0) acc = 0u;
        __syncthreads();
        unsigned int v = 0u;
        for (int j = threadIdx.x; j < 1024; j += blockDim.x) v |= w[2 * j + 1];
        atomicOr(&acc, v);
        __syncthreads();
        if (threadIdx.x == 0) g_is64 = (acc == 0u) ? 1 : 0;
    }
}

__device__ __forceinline__ int load_edge(const void* ei, long long idx) {
    if (g_is64) return (int)((const long long*)ei)[idx];
    return ((const int*)ei)[idx];
}

__global__ void k_count(const void* __restrict__ ei, int E) {
    int e = blockIdx.x * blockDim.x + threadIdx.x;
    if (e >= E) return;
    int d = load_edge(ei, (long long)E + e);
    if ((unsigned)d < (unsigned)N_NODES) atomicAdd(&g_cnt[d], 1);
}

__global__ void k_scan1() {
    __shared__ int sm[2][1024];
    int t = threadIdx.x;
    int gid = blockIdx.x * 1024 + t;
    int v = (gid < N_NODES) ? g_cnt[gid] : 0;
    int buf = 0;
    sm[0][t] = v;
    __syncthreads();
    for (int off = 1; off < 1024; off <<= 1) {
        int nv = sm[buf][t];
        if (t >= off) nv += sm[buf][t - off];
        sm[buf ^ 1][t] = nv;
        buf ^= 1;
        __syncthreads();
    }
    int inc = sm[buf][t];
    if (gid < N_NODES) g_row[gid + 1] = inc;
    if (t == 1023) g_bsums[blockIdx.x] = inc;
}

__global__ void k_scan2(int nb) {
    if (threadIdx.x == 0 && blockIdx.x == 0) {
        int acc = 0;
        for (int b = 0; b < nb; b++) { g_boffs[b] = acc; acc += g_bsums[b]; }
    }
}

__global__ void k_scan3() {
    int gid = blockIdx.x * 1024 + threadIdx.x;
    if (gid < N_NODES) {
        g_row[gid + 1] += g_boffs[blockIdx.x];
        g_di[gid] = rsqrtf((float)(g_cnt[gid] + 1));  // +1 self loop
    }
    if (gid == 0) g_row[0] = 0;
}

__global__ void k_scatter(const void* __restrict__ ei, int E) {
    int e = blockIdx.x * blockDim.x + threadIdx.x;
    if (e >= E) return;
    int s = load_edge(ei, e);
    int d = load_edge(ei, (long long)E + e);
    if ((unsigned)s >= (unsigned)N_NODES || (unsigned)d >= (unsigned)N_NODES) return;
    int pos = g_row[d] + atomicAdd(&g_cur[d], 1);
    g_epack[pos] = make_int2(s, __float_as_int(g_di[s] * g_di[d]));
}

// ---------------- gather helper: aggregate one node row (128 feats) ----
__device__ __forceinline__ float4 agg_node(const uint2* __restrict__ hp,
                                           int node, int lane, float4 b) {
    float di = g_di[node];
    float sn = di * di;
    uint2 su = hp[(size_t)node * 32 + lane];
    float2 s0 = __half22float2(*(const __half2*)&su.x);
    float2 s1 = __half22float2(*(const __half2*)&su.y);
    float4 acc = make_float4(s0.x * sn, s0.y * sn, s1.x * sn, s1.y * sn);
    int e = g_row[node], end = g_row[node + 1];
    for (; e + 3 < end; e += 4) {
        int2 p0 = g_epack[e];
        int2 p1 = g_epack[e + 1];
        int2 p2 = g_epack[e + 2];
        int2 p3 = g_epack[e + 3];
        uint2 u0 = hp[(size_t)p0.x * 32 + lane];
        uint2 u1 = hp[(size_t)p1.x * 32 + lane];
        uint2 u2 = hp[(size_t)p2.x * 32 + lane];
        uint2 u3 = hp[(size_t)p3.x * 32 + lane];
        float w0 = __int_as_float(p0.y), w1 = __int_as_float(p1.y);
        float w2 = __int_as_float(p2.y), w3 = __int_as_float(p3.y);
        {
            float2 a = __half22float2(*(const __half2*)&u0.x);
            float2 c = __half22float2(*(const __half2*)&u0.y);
            acc.x = fmaf(a.x, w0, acc.x); acc.y = fmaf(a.y, w0, acc.y);
            acc.z = fmaf(c.x, w0, acc.z); acc.w = fmaf(c.y, w0, acc.w);
        }
        {
            float2 a = __half22float2(*(const __half2*)&u1.x);
            float2 c = __half22float2(*(const __half2*)&u1.y);
            acc.x = fmaf(a.x, w1, acc.x); acc.y = fmaf(a.y, w1, acc.y);
            acc.z = fmaf(c.x, w1, acc.z); acc.w = fmaf(c.y, w1, acc.w);
        }
        {
            float2 a = __half22float2(*(const __half2*)&u2.x);
            float2 c = __half22float2(*(const __half2*)&u2.y);
            acc.x = fmaf(a.x, w2, acc.x); acc.y = fmaf(a.y, w2, acc.y);
            acc.z = fmaf(c.x, w2, acc.z); acc.w = fmaf(c.y, w2, acc.w);
        }
        {
            float2 a = __half22float2(*(const __half2*)&u3.x);
            float2 c = __half22float2(*(const __half2*)&u3.y);
            acc.x = fmaf(a.x, w3, acc.x); acc.y = fmaf(a.y, w3, acc.y);
            acc.z = fmaf(c.x, w3, acc.z); acc.w = fmaf(c.y, w3, acc.w);
        }
    }
    for (; e < end; e++) {
        int2 p = g_epack[e];
        uint2 u = hp[(size_t)p.x * 32 + lane];
        float wt = __int_as_float(p.y);
        float2 a = __half22float2(*(const __half2*)&u.x);
        float2 c = __half22float2(*(const __half2*)&u.y);
        acc.x = fmaf(a.x, wt, acc.x); acc.y = fmaf(a.y, wt, acc.y);
        acc.z = fmaf(c.x, wt, acc.z); acc.w = fmaf(c.y, wt, acc.w);
    }
    acc.x = fmaxf(acc.x + b.x, 0.f);
    acc.y = fmaxf(acc.y + b.y, 0.f);
    acc.z = fmaxf(acc.z + b.z, 0.f);
    acc.w = fmaxf(acc.w + b.w, 0.f);
    return acc;
}

// ---------------- fused: Hout[n,FO] = relu(agg(Hin)+bias) @ W ----------
// 64 nodes/block, 512 threads. Phase 1: 16 warps gather-aggregate 4 nodes
// each into smem A-tile. Phase 2: FFMA2 GEMM (proven mapping) -> fp16 out.
template <int FO>
__global__ void __launch_bounds__(512, 2)
k_agg_gemm(const __half* __restrict__ Hin, const float* __restrict__ bias,
           const float* __restrict__ W, __half* __restrict__ Hout, int n) {
    extern __shared__ float smf[];
    float* Ws = smf;               // 128*FO
    float* As = smf + 128 * FO;    // 64*132
    const int tid = threadIdx.x;
    const int node0 = blockIdx.x * 64;

    for (int i = tid; i < 128 * FO / 4; i += 512)
        ((float4*)Ws)[i] = ((const float4*)W)[i];

    // gather phase
    {
        int warp = tid >> 5, lane = tid & 31;
        const uint2* hp = (const uint2*)Hin;
        float4 b = ((const float4*)bias)[lane];
#pragma unroll
        for (int j = 0; j < 4; j++) {
            int node = node0 + warp * 4 + j;
            float4 acc = make_float4(0.f, 0.f, 0.f, 0.f);
            if (node < n) acc = agg_node(hp, node, lane, b);
            *(float4*)(As + (warp * 4 + j) * 132 + lane * 4) = acc;
        }
    }
    __syncthreads();

    // GEMM phase: rows 0-31 -> warps 0-7, rows 32-63 -> warps 8-15
    const int row = (tid & 31) + ((tid >> 8) << 5);
    const int c0 = ((tid >> 5) & 7) * (FO / 8);
    constexpr int NP = FO / 16;
    unsigned long long acc[NP];
#pragma unroll
    for (int q = 0; q < NP; q++) acc[q] = 0ull;

    const float* arow = As + row * 132;
#pragma unroll 2
    for (int k4 = 0; k4 < 128; k4 += 4) {
        float4 av = *(const float4*)(arow + k4);
        float as[4] = {av.x, av.y, av.z, av.w};
#pragma unroll
        for (int j = 0; j < 4; j++) {
            unsigned long long a2 = pack2(as[j]);
            const ulonglong2* wv = (const ulonglong2*)(Ws + (k4 + j) * FO + c0);
#pragma unroll
            for (int q = 0; q < NP / 2; q++) {
                ulonglong2 w = wv[q];
                acc[2 * q]     = ffma2(a2, w.x, acc[2 * q]);
                acc[2 * q + 1] = ffma2(a2, w.y, acc[2 * q + 1]);
            }
        }
    }
    int gr = node0 + row;
    if (gr < n) {
        unsigned int hv[NP];
#pragma unroll
        for (int q = 0; q < NP; q++) {
            union { unsigned long long u; float2 f; } uu;
            uu.u = acc[q];
            __half2 h2 = __float22half2_rn(uu.f);
            hv[q] = *(unsigned int*)&h2;
        }
        unsigned int* hp = (unsigned int*)(Hout + (size_t)gr * FO + c0);
#pragma unroll
        for (int q = 0; q < NP / 4; q++)
            ((uint4*)hp)[q] = make_uint4(hv[4 * q], hv[4 * q + 1], hv[4 * q + 2], hv[4 * q + 3]);
    }
}

// ---------------- GEMM (layer1): H16 = A[n,128] @ W[128,128] ----------
__global__ void k_gemm1(const float* __restrict__ A, const float* __restrict__ W,
                        __half* __restrict__ H, int n) {
    constexpr int FO = 128;
    extern __shared__ float smf[];
    float* Ws = smf;               // 128*FO
    float* As = smf + 128 * FO;    // 32*132
    int row0 = blockIdx.x * 32;
    for (int i = threadIdx.x; i < 128 * FO / 4; i += 256)
        ((float4*)Ws)[i] = ((const float4*)W)[i];
    for (int i = threadIdx.x; i < 32 * 32; i += 256) {
        int r = i >> 5, c = i & 31;
        int gr = row0 + r;
        float4 v = (gr < n) ? ((const float4*)A)[(size_t)gr * 32 + c]
                            : make_float4(0.f, 0.f, 0.f, 0.f);
        *(float4*)(As + r * 132 + c * 4) = v;
    }
    __syncthreads();

    const int row = threadIdx.x & 31;
    const int c0 = (threadIdx.x >> 5) * (FO / 8);
    constexpr int NP = FO / 16;
    unsigned long long acc[NP];
#pragma unroll
    for (int q = 0; q < NP; q++) acc[q] = 0ull;

    const float* arow = As + row * 132;
#pragma unroll 2
    for (int k4 = 0; k4 < 128; k4 += 4) {
        float4 av = *(const float4*)(arow + k4);
        float as[4] = {av.x, av.y, av.z, av.w};
#pragma unroll
        for (int j = 0; j < 4; j++) {
            unsigned long long a2 = pack2(as[j]);
            const ulonglong2* wv = (const ulonglong2*)(Ws + (k4 + j) * FO + c0);
#pragma unroll
            for (int q = 0; q < NP / 2; q++) {
                ulonglong2 w = wv[q];
                acc[2 * q]     = ffma2(a2, w.x, acc[2 * q]);
                acc[2 * q + 1] = ffma2(a2, w.y, acc[2 * q + 1]);
            }
        }
    }
    int gr = row0 + row;
    if (gr < n) {
        unsigned int hv[NP];
#pragma unroll
        for (int q = 0; q < NP; q++) {
            union { unsigned long long u; float2 f; } uu;
            uu.u = acc[q];
            __half2 h2 = __float22half2_rn(uu.f);
            hv[q] = *(unsigned int*)&h2;
        }
        unsigned int* hp = (unsigned int*)(H + (size_t)gr * FO + c0);
#pragma unroll
        for (int q = 0; q < NP / 4; q++)
            ((uint4*)hp)[q] = make_uint4(hv[4 * q], hv[4 * q + 1], hv[4 * q + 2], hv[4 * q + 3]);
    }
}

// layer 3 final: aggregate (F=64, fp16 gathers) + bias + L2-norm -> x_emb.
__global__ void k_agg64n(const __half* __restrict__ h, const float* __restrict__ bias,
                         float* __restrict__ out, int n) {
    int node = (blockIdx.x * blockDim.x + threadIdx.x) >> 5;
    int lane = threadIdx.x & 31;
    if (node >= n) return;
    const unsigned int* hp = (const unsigned int*)h;
    float di = g_di[node];
    float sn = di * di;
    unsigned int su = hp[(size_t)node * 32 + lane];
    float2 sf = __half22float2(*(const __half2*)&su);
    float2 acc = make_float2(sf.x * sn, sf.y * sn);
    int e = g_row[node], end = g_row[node + 1];
    for (; e + 3 < end; e += 4) {
        int2 p0 = g_epack[e];
        int2 p1 = g_epack[e + 1];
        int2 p2 = g_epack[e + 2];
        int2 p3 = g_epack[e + 3];
        unsigned int u0 = hp[(size_t)p0.x * 32 + lane];
        unsigned int u1 = hp[(size_t)p1.x * 32 + lane];
        unsigned int u2 = hp[(size_t)p2.x * 32 + lane];
        unsigned int u3 = hp[(size_t)p3.x * 32 + lane];
        float w0 = __int_as_float(p0.y), w1 = __int_as_float(p1.y);
        float w2 = __int_as_float(p2.y), w3 = __int_as_float(p3.y);
        float2 v0 = __half22float2(*(const __half2*)&u0);
        float2 v1 = __half22float2(*(const __half2*)&u1);
        float2 v2 = __half22float2(*(const __half2*)&u2);
        float2 v3 = __half22float2(*(const __half2*)&u3);
        acc.x = fmaf(v0.x, w0, acc.x); acc.y = fmaf(v0.y, w0, acc.y);
        acc.x = fmaf(v1.x, w1, acc.x); acc.y = fmaf(v1.y, w1, acc.y);
        acc.x = fmaf(v2.x, w2, acc.x); acc.y = fmaf(v2.y, w2, acc.y);
        acc.x = fmaf(v3.x, w3, acc.x); acc.y = fmaf(v3.y, w3, acc.y);
    }
    for (; e < end; e++) {
        int2 p = g_epack[e];
        unsigned int u = hp[(size_t)p.x * 32 + lane];
        float wt = __int_as_float(p.y);
        float2 v = __half22float2(*(const __half2*)&u);
        acc.x = fmaf(v.x, wt, acc.x); acc.y = fmaf(v.y, wt, acc.y);
    }
    float2 b = ((const float2*)bias)[lane];
    acc.x += b.x;
    acc.y += b.y;
    float ss = acc.x * acc.x + acc.y * acc.y;
#pragma unroll
    for (int o = 16; o; o >>= 1) ss += __shfl_xor_sync(0xffffffffu, ss, o);
    float inv = 1.f / fmaxf(sqrtf(ss), 1e-12f);
    ((float2*)out)[(size_t)node * 32 + lane] = make_float2(acc.x * inv, acc.y * inv);
}

// ---------------- y branch ----------------
__global__ void k_y1(const float* __restrict__ y, const float* __restrict__ gamma,
                     const float* __restrict__ beta, const float* __restrict__ Wm1,
                     const float* __restrict__ bm1) {
    __shared__ float red[256];
    int t = threadIdx.x;
    float v = y[t];
    red[t] = v;
    __syncthreads();
    for (int s = 128; s; s >>= 1) { if (t < s) red[t] += red[t + s]; __syncthreads(); }
    float mu = red[0] * (1.f / 256.f);
    __syncthreads();
    red[t] = v * v;
    __syncthreads();
    for (int s = 128; s; s >>= 1) { if (t < s) red[t] += red[t + s]; __syncthreads(); }
    float var = red[0] * (1.f / 256.f) - mu * mu;
    float yb = (v - mu) * rsqrtf(var + 1e-5f) * gamma[0] + beta[0];
    for (int j = 0; j < 128; j++)
        g_t[t * 128 + j] = fmaxf(fmaf(yb, Wm1[j], bm1[j]), 0.f);
}

__global__ void k_y2(const float* __restrict__ Wm2, const float* __restrict__ bm2,
                     float* __restrict__ out) {
    __shared__ float ts[128];
    __shared__ float wsum[2];
    int i = blockIdx.x, c = threadIdx.x;
    ts[c] = g_t[i * 128 + c];
    ts[c + 64] = g_t[i * 128 + c + 64];
    __syncthreads();
    float a = bm2[c];
#pragma unroll 4
    for (int j = 0; j < 128; j++) a = fmaf(ts[j], Wm2[j * 64 + c], a);
    float ss = a * a;
#pragma unroll
    for (int o = 16; o; o >>= 1) ss += __shfl_xor_sync(0xffffffffu, ss, o);
    if ((c & 31) == 0) wsum[c >> 5] = ss;
    __syncthreads();
    float inv = 1.f / fmaxf(sqrtf(wsum[0] + wsum[1]), 1e-12f);
    out[i * 64 + c] = a * inv;
}

// ---------------- launch ----------------
extern "C" void kernel_launch(void* const* d_in, const int* in_sizes, int n_in,
                              void* d_out, int out_size) {
    const float* x  = (const float*)d_in[0];
    const float* y  = (const float*)d_in[1];
    const void*  ei = d_in[2];
    const float* W1 = (const float*)d_in[3];  const float* b1  = (const float*)d_in[4];
    const float* W2 = (const float*)d_in[5];  const float* b2  = (const float*)d_in[6];
    const float* W3 = (const float*)d_in[7];  const float* b3  = (const float*)d_in[8];
    const float* bg = (const float*)d_in[9];  const float* bb  = (const float*)d_in[10];
    const float* Wm1 = (const float*)d_in[11]; const float* bm1 = (const float*)d_in[12];
    const float* Wm2 = (const float*)d_in[13]; const float* bm2 = (const float*)d_in[14];
    float* out = (float*)d_out;

    const int n = N_NODES;
    const int E = in_sizes[2] / 2;

    const size_t smG1  = 128 * 128 * 4 + 32 * 132 * 4;
    const size_t smF128 = 128 * 128 * 4 + 64 * 132 * 4;
    const size_t smF64  = 128 * 64 * 4 + 64 * 132 * 4;
    cudaFuncSetAttribute(k_gemm1, cudaFuncAttributeMaxDynamicSharedMemorySize, (int)smG1);
    cudaFuncSetAttribute(k_agg_gemm<128>, cudaFuncAttributeMaxDynamicSharedMemorySize, (int)smF128);
    cudaFuncSetAttribute(k_agg_gemm<64>,  cudaFuncAttributeMaxDynamicSharedMemorySize, (int)smF64);

    void *pA, *pB;
    cudaGetSymbolAddress(&pA, g_h16a);
    cudaGetSymbolAddress(&pB, g_h16b);
    __half* hA = (__half*)pA;
    __half* hB = (__half*)pB;

    const int gb1 = (n + 31) / 32;
    const int gbF = (n + 63) / 64;
    const int aggBlocks = (n * 32 + 255) / 256;
    const int NB = (n + 1023) / 1024;  // 49

    // fork: side stream runs GEMM1 + y-branch concurrently with CSR build
    cudaStream_t s2;
    cudaEvent_t evFork, evJoin;
    cudaStreamCreateWithFlags(&s2, cudaStreamNonBlocking);
    cudaEventCreateWithFlags(&evFork, cudaEventDisableTiming);
    cudaEventCreateWithFlags(&evJoin, cudaEventDisableTiming);

    cudaEventRecord(evFork, 0);
    cudaStreamWaitEvent(s2, evFork, 0);

    k_gemm1<<<gb1, 256, smG1, s2>>>(x, W1, hA, n);
    k_y1<<<1, 256, 0, s2>>>(y, bg, bb, Wm1, bm1);
    k_y2<<<M_Y, 64, 0, s2>>>(Wm2, bm2, out + (size_t)N_NODES * 64);
    cudaEventRecord(evJoin, s2);

    // main stream: CSR build
    k_init<<<(n + 255) / 256, 256>>>((const unsigned int*)ei);
    k_count<<<(E + 255) / 256, 256>>>(ei, E);
    k_scan1<<<NB, 1024>>>();
    k_scan2<<<1, 32>>>(NB);
    k_scan3<<<NB, 1024>>>();
    k_scatter<<<(E + 255) / 256, 256>>>(ei, E);

    cudaStreamWaitEvent(0, evJoin, 0);

    // fused layers
    k_agg_gemm<128><<<gbF, 512, smF128>>>(hA, b1, W2, hB, n);  // layer1 agg + GEMM2
    k_agg_gemm<64><<<gbF, 512, smF64>>>(hB, b2, W3, hA, n);    // layer2 agg + GEMM3
    k_agg64n<<<aggBlocks, 256>>>(hA, b3, out, n);              // layer3 agg + normalize

    cudaEventDestroy(evFork);
    cudaEventDestroy(evJoin);
    cudaStreamDestroy(s2);
}